// round 13
// baseline (speedup 1.0000x reference)
#include <cuda_runtime.h>
#include <cuda_bf16.h>
#include <cuda_fp16.h>
#include <math.h>
#include <stdint.h>

#define BATCH 8
#define CDIM  256
#define NDIM  4096
#define CQKD  32
#define ATT_SCALE 0.1767766952966369f   // 1/sqrt(32)

// ---------------- scratch (device globals) ------------------------------------
__device__ __half g_q[(size_t)BATCH * NDIM * CQKD];           // q fp16
__device__ __half g_k[(size_t)BATCH * NDIM * CQKD];           // k fp16
__device__ __half g_vh[(size_t)BATCH * CDIM * NDIM];          // V fp16
__device__ __half g_ah[(size_t)BATCH * NDIM * NDIM];          // attn fp16
__device__ float g_attn_fb[(size_t)BATCH * NDIM * NDIM];      // fallback
__device__ float g_tex_fb[(size_t)BATCH * CDIM * NDIM];       // fallback

// =============================== PTX helpers ==================================
__device__ __forceinline__ uint32_t smem_u32(const void* p) {
    uint32_t a;
    asm("{ .reg .u64 t; cvta.to.shared.u64 t, %1; cvt.u32.u64 %0, t; }"
        : "=r"(a) : "l"(p));
    return a;
}
__device__ __forceinline__ void cp16(uint32_t dst, const void* src) {
    asm volatile("cp.async.cg.shared.global [%0], [%1], 16;" :: "r"(dst), "l"(src) : "memory");
}
#define CP_COMMIT() asm volatile("cp.async.commit_group;" ::: "memory")
#define CP_WAIT1()  asm volatile("cp.async.wait_group 1;"  ::: "memory")
#define CP_WAIT2()  asm volatile("cp.async.wait_group 2;"  ::: "memory")
#define CP_WAIT0()  asm volatile("cp.async.wait_group 0;"  ::: "memory")

__device__ __forceinline__ void ldm_x4(uint32_t* r, uint32_t addr) {
    asm volatile("ldmatrix.sync.aligned.m8n8.x4.shared.b16 {%0,%1,%2,%3}, [%4];"
        : "=r"(r[0]), "=r"(r[1]), "=r"(r[2]), "=r"(r[3]) : "r"(addr));
}
__device__ __forceinline__ void ldm_x4_t(uint32_t* r, uint32_t addr) {
    asm volatile("ldmatrix.sync.aligned.m8n8.x4.trans.shared.b16 {%0,%1,%2,%3}, [%4];"
        : "=r"(r[0]), "=r"(r[1]), "=r"(r[2]), "=r"(r[3]) : "r"(addr));
}
__device__ __forceinline__ void mma_bf16(float* c, const uint32_t* a, const uint32_t* b) {
    asm volatile(
        "mma.sync.aligned.m16n8k16.row.col.f32.bf16.bf16.f32 "
        "{%0,%1,%2,%3}, {%4,%5,%6,%7}, {%8,%9}, {%0,%1,%2,%3};"
        : "+f"(c[0]), "+f"(c[1]), "+f"(c[2]), "+f"(c[3])
        : "r"(a[0]), "r"(a[1]), "r"(a[2]), "r"(a[3]), "r"(b[0]), "r"(b[1]));
}
__device__ __forceinline__ void mma_f16(float* c, const uint32_t* a, const uint32_t* b) {
    asm volatile(
        "mma.sync.aligned.m16n8k16.row.col.f32.f16.f16.f32 "
        "{%0,%1,%2,%3}, {%4,%5,%6,%7}, {%8,%9}, {%0,%1,%2,%3};"
        : "+f"(c[0]), "+f"(c[1]), "+f"(c[2]), "+f"(c[3])
        : "r"(a[0]), "r"(a[1]), "r"(a[2]), "r"(a[3]), "r"(b[0]), "r"(b[1]));
}
__device__ __forceinline__ uint32_t bfpack(float x, float y) {
    __nv_bfloat162 h = __floats2bfloat162_rn(x, y);
    return *(uint32_t*)&h;
}
__device__ __forceinline__ void split2(float x, float y, uint32_t& hi, uint32_t& lo) {
    __nv_bfloat16 hx = __float2bfloat16(x);
    __nv_bfloat16 hy = __float2bfloat16(y);
    float lx = x - __bfloat162float(hx);
    float ly = y - __bfloat162float(hy);
    __nv_bfloat162 hp; hp.x = hx; hp.y = hy;
    hi = *(uint32_t*)&hp;
    lo = bfpack(lx, ly);
}

// ---------------- q / k projection -> fp16 plane -------------------------------
__global__ void proj_small_kernel(const float* __restrict__ X,
                                  const float* __restrict__ W,
                                  const float* __restrict__ bias,
                                  __half* __restrict__ Y)
{
    __shared__ float Ws[CQKD * CDIM];
    int tid = threadIdx.x;
    for (int i = tid; i < CQKD * CDIM; i += 256) Ws[i] = W[i];
    __syncthreads();

    int b = blockIdx.y;
    int n = blockIdx.x * 256 + tid;
    const float* Xp = X + (size_t)b * CDIM * NDIM + n;

    float acc[CQKD];
#pragma unroll
    for (int o = 0; o < CQKD; o++) acc[o] = bias[o];

    for (int c = 0; c < CDIM; c++) {
        float x = Xp[(size_t)c * NDIM];
#pragma unroll
        for (int o = 0; o < CQKD; o++) acc[o] += x * Ws[o * CDIM + c];
    }
    size_t base = ((size_t)b * NDIM + n) * CQKD;
    uint32_t* ph = (uint32_t*)(Y + base);
#pragma unroll
    for (int o = 0; o < CQKD; o += 2) {
        __half2 h = __floats2half2_rn(acc[o], acc[o + 1]);
        ph[o >> 1] = *(uint32_t*)&h;
    }
}

// ============== proj_v via 3xBF16 mma: V[c,n] = Wv[c,:].X[:,n] + bv ============
#define PV_AP  5120
#define PV_XP  8704
#define PV_A_OFF  0
#define PV_X_OFF  (2 * PV_AP)
#define PV_SMEM   (PV_X_OFF + 2 * PV_XP)

__global__ void __launch_bounds__(256, 2)
proj_v_mma_kernel(const float* __restrict__ X,
                  const float* __restrict__ Wv,
                  const float* __restrict__ bv,
                  __half* __restrict__ VH)
{
    __shared__ __align__(16) char sm[PV_SMEM];
    uint32_t sb = smem_u32(sm);
    int tid = threadIdx.x;
    int wid = tid >> 5, lid = tid & 31;
    int g = lid >> 2, t = lid & 3;
    int wm = wid & 1, wn = wid >> 1;

    int b  = blockIdx.z;
    int m0 = blockIdx.y * 64;
    int n0 = blockIdx.x * 128;

    const float* Xb = X + (size_t)b * CDIM * NDIM;

    int am = tid >> 2, aq = tid & 3;
    int xk = tid >> 3, xq = (tid & 7) * 16;

    float4 wreg[2], xreg[4];
    {
        const float* wp = Wv + (size_t)(m0 + am) * CDIM + aq * 8;
        wreg[0] = *(const float4*)(wp);
        wreg[1] = *(const float4*)(wp + 4);
        const float* xp = Xb + (size_t)xk * NDIM + n0 + xq;
#pragma unroll
        for (int i = 0; i < 4; i++) xreg[i] = *(const float4*)(xp + i * 4);
    }

    float acc[2][4][4];
#pragma unroll
    for (int mt = 0; mt < 2; mt++)
#pragma unroll
        for (int nt = 0; nt < 4; nt++)
#pragma unroll
            for (int q = 0; q < 4; q++) acc[mt][nt][q] = 0.f;

    uint32_t a_lane = (uint32_t)(lid & 15) * 80 + (uint32_t)(lid >> 4) * 16;
    uint32_t bt_lane = (uint32_t)((lid & 7) + ((lid >> 3) & 1) * 8) * 272
                     + (uint32_t)(lid >> 4) * 16;

    for (int kc = 0; kc < 8; kc++) {
        {
            uint32_t ad = (uint32_t)PV_A_OFF + (uint32_t)am * 80 + aq * 16;
            float av[8] = {wreg[0].x, wreg[0].y, wreg[0].z, wreg[0].w,
                           wreg[1].x, wreg[1].y, wreg[1].z, wreg[1].w};
#pragma unroll
            for (int i = 0; i < 4; i++) {
                uint32_t hi, lo;
                split2(av[2 * i], av[2 * i + 1], hi, lo);
                *(uint32_t*)(sm + ad + i * 4) = hi;
                *(uint32_t*)(sm + ad + PV_AP + i * 4) = lo;
            }
            uint32_t xd = (uint32_t)PV_X_OFF + (uint32_t)xk * 272 + xq * 2;
            float xv[16] = {xreg[0].x, xreg[0].y, xreg[0].z, xreg[0].w,
                            xreg[1].x, xreg[1].y, xreg[1].z, xreg[1].w,
                            xreg[2].x, xreg[2].y, xreg[2].z, xreg[2].w,
                            xreg[3].x, xreg[3].y, xreg[3].z, xreg[3].w};
#pragma unroll
            for (int i = 0; i < 8; i++) {
                uint32_t hi, lo;
                split2(xv[2 * i], xv[2 * i + 1], hi, lo);
                *(uint32_t*)(sm + xd + i * 4) = hi;
                *(uint32_t*)(sm + xd + PV_XP + i * 4) = lo;
            }
        }
        __syncthreads();

        if (kc < 7) {
            const float* wp = Wv + (size_t)(m0 + am) * CDIM + (kc + 1) * 32 + aq * 8;
            wreg[0] = *(const float4*)(wp);
            wreg[1] = *(const float4*)(wp + 4);
            const float* xp = Xb + (size_t)((kc + 1) * 32 + xk) * NDIM + n0 + xq;
#pragma unroll
            for (int i = 0; i < 4; i++) xreg[i] = *(const float4*)(xp + i * 4);
        }

#pragma unroll
        for (int ks = 0; ks < 2; ks++) {
            uint32_t ah[2][4], al[2][4];
#pragma unroll
            for (int mt = 0; mt < 2; mt++) {
                uint32_t ro = (uint32_t)(wm * 32 + mt * 16) * 80 + ks * 32 + a_lane;
                ldm_x4(ah[mt], sb + PV_A_OFF + ro);
                ldm_x4(al[mt], sb + PV_A_OFF + PV_AP + ro);
            }
            uint32_t bh[2][4], bl[2][4];
#pragma unroll
            for (int p = 0; p < 2; p++) {
                uint32_t ro = (uint32_t)(ks * 16) * 272 + (uint32_t)(wn * 32 + p * 16) * 2 + bt_lane;
                ldm_x4_t(bh[p], sb + PV_X_OFF + ro);
                ldm_x4_t(bl[p], sb + PV_X_OFF + PV_XP + ro);
            }
#pragma unroll
            for (int mt = 0; mt < 2; mt++)
#pragma unroll
                for (int nt = 0; nt < 4; nt++) {
                    const uint32_t* bhp = &bh[nt >> 1][(nt & 1) * 2];
                    const uint32_t* blp = &bl[nt >> 1][(nt & 1) * 2];
                    mma_bf16(acc[mt][nt], ah[mt], bhp);
                    mma_bf16(acc[mt][nt], ah[mt], blp);
                    mma_bf16(acc[mt][nt], al[mt], bhp);
                }
        }
        __syncthreads();
    }

#pragma unroll
    for (int mt = 0; mt < 2; mt++) {
        int r0 = m0 + wm * 32 + mt * 16 + g;
        float b0 = bv[r0], b1 = bv[r0 + 8];
#pragma unroll
        for (int nt = 0; nt < 4; nt++) {
            int col = n0 + wn * 32 + nt * 8 + 2 * t;
            size_t off0 = ((size_t)b * CDIM + r0) * NDIM + col;
            size_t off1 = ((size_t)b * CDIM + r0 + 8) * NDIM + col;
            __half2 h0 = __floats2half2_rn(acc[mt][nt][0] + b0, acc[mt][nt][1] + b0);
            __half2 h1 = __floats2half2_rn(acc[mt][nt][2] + b1, acc[mt][nt][3] + b1);
            *(uint32_t*)(VH + off0) = *(uint32_t*)&h0;
            *(uint32_t*)(VH + off1) = *(uint32_t*)&h1;
        }
    }
}

// ======== fused energy + softmax via fp16 mma (no max; |E·scale| < ~1) ========
#define QPLANE 10240
#define KPLANE 5120
#define FK_K_OFF   QPLANE
#define FK_RS_OFF  (FK_K_OFF + 3 * KPLANE)
#define FK_INV_OFF (FK_RS_OFF + 128 * 4 * 4)
#define FK_SMEM    (FK_INV_OFF + 128 * 4)
#define FK_NCH (NDIM / 64)

__device__ __forceinline__ void fk_load_k(int j, uint32_t sb, int tid,
                                          const __half* Kb)
{
    uint32_t st = sb + FK_K_OFF + (uint32_t)(j % 3) * KPLANE;
    int row = tid >> 2;
    int q   = tid & 3;
    cp16(st + (uint32_t)row * 80 + q * 16,
         Kb + (size_t)(j * 64 + row) * CQKD + q * 8);
}

__global__ void __launch_bounds__(256, 2)
attn_fused_kernel(const __half* __restrict__ Q,
                  const __half* __restrict__ K,
                  float* __restrict__ A,
                  __half* __restrict__ AH)
{
    __shared__ __align__(16) char smem[FK_SMEM];
    uint32_t sb = smem_u32(smem);
    float* rs  = (float*)(smem + FK_RS_OFF);
    float* inv = (float*)(smem + FK_INV_OFF);

    int tid = threadIdx.x;
    int wid = tid >> 5, lid = tid & 31;
    int g = lid >> 2, t = lid & 3;
    int wm = wid & 1, wn = wid >> 1;

    int b  = blockIdx.y;
    int m0 = blockIdx.x * 128;

    const __half* Kb = K + (size_t)b * NDIM * CQKD;

    {
        int row  = tid >> 1;
        int half = tid & 1;
        const __half* s0 = Q + ((size_t)b * NDIM + m0 + row) * CQKD + half * 16;
        uint32_t d = sb + (uint32_t)row * 80 + half * 32;
        cp16(d, s0); cp16(d + 16, s0 + 8);
    }

    uint32_t a_lane = (uint32_t)(lid & 15) * 80 + (uint32_t)(lid >> 4) * 16;
    uint32_t b_lane = (uint32_t)((lid & 7) + (lid >> 4) * 8) * 80
                    + (uint32_t)((lid >> 3) & 1) * 16;

    float rsum0[4] = {0.f, 0.f, 0.f, 0.f};
    float rsum1[4] = {0.f, 0.f, 0.f, 0.f};

    for (int pass = 0; pass < 2; pass++) {
        fk_load_k(0, sb, tid, Kb); CP_COMMIT();
        fk_load_k(1, sb, tid, Kb); CP_COMMIT();

        for (int j = 0; j < FK_NCH; j++) {
            CP_WAIT1();
            __syncthreads();

            uint32_t kst = sb + FK_K_OFF + (uint32_t)(j % 3) * KPLANE;
            float acc[4][2][4];
#pragma unroll
            for (int mt = 0; mt < 4; mt++)
#pragma unroll
                for (int nt = 0; nt < 2; nt++)
#pragma unroll
                    for (int q = 0; q < 4; q++) acc[mt][nt][q] = 0.f;

#pragma unroll
            for (int ks = 0; ks < 2; ks++) {
                uint32_t af[4][4];
#pragma unroll
                for (int mt = 0; mt < 4; mt++)
                    ldm_x4(af[mt], sb + (uint32_t)(wm * 64 + mt * 16) * 80 + ks * 32 + a_lane);
                uint32_t bf[4];
                ldm_x4(bf, kst + (uint32_t)(wn * 16) * 80 + ks * 32 + b_lane);
#pragma unroll
                for (int mt = 0; mt < 4; mt++)
#pragma unroll
                    for (int nt = 0; nt < 2; nt++)
                        mma_f16(acc[mt][nt], af[mt], &bf[nt * 2]);
            }
            __syncthreads();
            if (j + 2 < FK_NCH) fk_load_k(j + 2, sb, tid, Kb);
            CP_COMMIT();

            if (pass == 0) {
#pragma unroll
                for (int mt = 0; mt < 4; mt++) {
                    float s0 = 0.f, s1 = 0.f;
#pragma unroll
                    for (int nt = 0; nt < 2; nt++) {
                        s0 += __expf(acc[mt][nt][0] * ATT_SCALE) + __expf(acc[mt][nt][1] * ATT_SCALE);
                        s1 += __expf(acc[mt][nt][2] * ATT_SCALE) + __expf(acc[mt][nt][3] * ATT_SCALE);
                    }
                    s0 += __shfl_xor_sync(0xffffffffu, s0, 1);
                    s0 += __shfl_xor_sync(0xffffffffu, s0, 2);
                    s1 += __shfl_xor_sync(0xffffffffu, s1, 1);
                    s1 += __shfl_xor_sync(0xffffffffu, s1, 2);
                    rsum0[mt] += s0;
                    rsum1[mt] += s1;
                }
            } else {
#pragma unroll
                for (int mt = 0; mt < 4; mt++) {
                    int r0 = m0 + wm * 64 + mt * 16 + g;
                    float i0 = inv[wm * 64 + mt * 16 + g];
                    float i1 = inv[wm * 64 + mt * 16 + g + 8];
#pragma unroll
                    for (int nt = 0; nt < 2; nt++) {
                        int col = j * 64 + wn * 16 + nt * 8 + 2 * t;
                        float p0 = __expf(acc[mt][nt][0] * ATT_SCALE) * i0;
                        float p1 = __expf(acc[mt][nt][1] * ATT_SCALE) * i0;
                        float p2 = __expf(acc[mt][nt][2] * ATT_SCALE) * i1;
                        float p3 = __expf(acc[mt][nt][3] * ATT_SCALE) * i1;
                        size_t off0 = ((size_t)b * NDIM + r0) * NDIM + col;
                        size_t off1 = ((size_t)b * NDIM + r0 + 8) * NDIM + col;
                        float2 f0 = {p0, p1};
                        float2 f1 = {p2, p3};
                        *(float2*)(A + off0) = f0;
                        *(float2*)(A + off1) = f1;
                        __half2 h0 = __floats2half2_rn(p0, p1);
                        __half2 h1 = __floats2half2_rn(p2, p3);
                        *(uint32_t*)(AH + off0) = *(uint32_t*)&h0;
                        *(uint32_t*)(AH + off1) = *(uint32_t*)&h1;
                    }
                }
            }
        }

        if (pass == 0) {
            CP_WAIT0();
            __syncthreads();
            if (t == 0) {
#pragma unroll
                for (int mt = 0; mt < 4; mt++) {
                    rs[(wm * 64 + mt * 16 + g) * 4 + wn]     = rsum0[mt];
                    rs[(wm * 64 + mt * 16 + g + 8) * 4 + wn] = rsum1[mt];
                }
            }
            __syncthreads();
            if (tid < 128)
                inv[tid] = 1.0f / (rs[tid * 4] + rs[tid * 4 + 1] + rs[tid * 4 + 2] + rs[tid * 4 + 3]);
            __syncthreads();
        }
    }
}

// ============== texture GEMM via fp16 mma, K-chunks of 32, 4-stage =============
// tex[b,c,m] = sum_n V[b,c,n] * attn[b,m,n];  out = tex + sketches
#define EPLANE 10240                    // 128 rows x 80B
#define XSTAGE_BYTES (2 * EPLANE)       // V plane + A plane -> 20480
#define XSTAGES 4
#define XSMEM_BYTES (XSTAGES * XSTAGE_BYTES)   // 81920
#define XNCH (NDIM / 32)                // 128

__device__ __forceinline__ void x_load_chunk(int j, uint32_t sb_base, int tid,
                                             const __half* VHb, const __half* AHb)
{
    uint32_t sb = sb_base + (uint32_t)(j & (XSTAGES - 1)) * XSTAGE_BYTES;
    int row  = tid >> 1;
    int half = tid & 1;
    int kt = j * 32;

    const __half* s0 = VHb + (size_t)row * NDIM + kt + half * 16;
    const __half* s1 = AHb + (size_t)row * NDIM + kt + half * 16;
    uint32_t d0 = sb + (uint32_t)row * 80 + half * 32;
    uint32_t d1 = d0 + EPLANE;
    cp16(d0, s0); cp16(d0 + 16, s0 + 8);
    cp16(d1, s1); cp16(d1 + 16, s1 + 8);
}

__global__ void __launch_bounds__(256, 2)
texture_mma_kernel(const __half* __restrict__ VH,
                   const __half* __restrict__ AH,
                   const float* __restrict__ SK,
                   float* __restrict__ TEX,
                   float* __restrict__ OUT)
{
    extern __shared__ char smem[];
    uint32_t sb_base = smem_u32(smem);
    int tid = threadIdx.x;
    int wid = tid >> 5, lid = tid & 31;
    int g = lid >> 2, t = lid & 3;
    int wm = wid & 1, wn = wid >> 1;

    int b  = blockIdx.z;
    int i0 = blockIdx.y * 128;
    int j0 = blockIdx.x * 128;

    const __half* VHb = VH + ((size_t)b * CDIM + i0) * NDIM;
    const __half* AHb = AH + ((size_t)b * NDIM + j0) * NDIM;

    float acc[4][4][4];
#pragma unroll
    for (int mt = 0; mt < 4; mt++)
#pragma unroll
        for (int nt = 0; nt < 4; nt++)
#pragma unroll
            for (int q = 0; q < 4; q++) acc[mt][nt][q] = 0.f;

    x_load_chunk(0, sb_base, tid, VHb, AHb); CP_COMMIT();
    x_load_chunk(1, sb_base, tid, VHb, AHb); CP_COMMIT();
    x_load_chunk(2, sb_base, tid, VHb, AHb); CP_COMMIT();

    uint32_t a_lane = (uint32_t)(lid & 15) * 80 + (uint32_t)(lid >> 4) * 16;
    uint32_t b_lane = (uint32_t)((lid & 7) + ((lid >> 4) * 8)) * 80
                    + (uint32_t)((lid >> 3) & 1) * 16;

    for (int i = 0; i < XNCH; i++) {
        CP_WAIT2();
        __syncthreads();
        if (i + 3 < XNCH) x_load_chunk(i + 3, sb_base, tid, VHb, AHb);
        CP_COMMIT();

        uint32_t sA = sb_base + (uint32_t)(i & (XSTAGES - 1)) * XSTAGE_BYTES;
        uint32_t sB = sA + EPLANE;

#pragma unroll
        for (int ks = 0; ks < 2; ks++) {
            uint32_t af[4][4];
#pragma unroll
            for (int mt = 0; mt < 4; mt++)
                ldm_x4(af[mt], sA + (uint32_t)(wm * 64 + mt * 16) * 80 + ks * 32 + a_lane);
            uint32_t bq[2][4];
#pragma unroll
            for (int p = 0; p < 2; p++)
                ldm_x4(bq[p], sB + (uint32_t)(wn * 32 + p * 16) * 80 + ks * 32 + b_lane);
#pragma unroll
            for (int mt = 0; mt < 4; mt++)
#pragma unroll
                for (int nt = 0; nt < 4; nt++)
                    mma_f16(acc[mt][nt], af[mt], &bq[nt >> 1][(nt & 1) * 2]);
        }
        __syncthreads();
    }
    CP_WAIT0();

#pragma unroll
    for (int mt = 0; mt < 4; mt++) {
        int r0 = i0 + wm * 64 + mt * 16 + g;
#pragma unroll
        for (int nt = 0; nt < 4; nt++) {
            int col = j0 + wn * 32 + nt * 8 + 2 * t;
            size_t off0 = ((size_t)b * CDIM + r0) * NDIM + col;
            size_t off1 = ((size_t)b * CDIM + r0 + 8) * NDIM + col;
            float2 t0 = {acc[mt][nt][0], acc[mt][nt][1]};
            float2 t1 = {acc[mt][nt][2], acc[mt][nt][3]};
            float2 s0 = *(const float2*)(SK + off0);
            float2 s1 = *(const float2*)(SK + off1);
            *(float2*)(TEX + off0) = t0;
            *(float2*)(TEX + off1) = t1;
            float2 o0 = {t0.x + s0.x, t0.y + s0.y};
            float2 o1 = {t1.x + s1.x, t1.y + s1.y};
            *(float2*)(OUT + off0) = o0;
            *(float2*)(OUT + off1) = o1;
        }
    }
}

// ---------------- launch -------------------------------------------------------
extern "C" void kernel_launch(void* const* d_in, const int* in_sizes, int n_in,
                              void* d_out, int out_size)
{
    const float* sk = (const float*)d_in[0];
    const float* ex = (const float*)d_in[1];
    const float* Wq = (const float*)d_in[2];
    const float* bq = (const float*)d_in[3];
    const float* Wk = (const float*)d_in[4];
    const float* bk = (const float*)d_in[5];
    const float* Wv = (const float*)d_in[6];
    const float* bv = (const float*)d_in[7];

    const size_t BCN = (size_t)BATCH * CDIM * NDIM;
    const size_t BNN = (size_t)BATCH * NDIM * NDIM;

    float* out_p = (float*)d_out;
    float* tex_p;
    float* attn_p;

    if ((size_t)(unsigned)out_size >= 2 * BCN + BNN) {
        tex_p  = out_p + BCN;
        attn_p = out_p + 2 * BCN;
    } else {
        void* p;
        cudaGetSymbolAddress(&p, g_tex_fb);  tex_p  = (float*)p;
        cudaGetSymbolAddress(&p, g_attn_fb); attn_p = (float*)p;
    }

    __half *q_p, *k_p, *vh, *ah;
    { void* p;
      cudaGetSymbolAddress(&p, g_q);  q_p = (__half*)p;
      cudaGetSymbolAddress(&p, g_k);  k_p = (__half*)p;
      cudaGetSymbolAddress(&p, g_vh); vh  = (__half*)p;
      cudaGetSymbolAddress(&p, g_ah); ah  = (__half*)p; }

    // 1) q, k projections -> fp16
    dim3 gproj(NDIM / 256, BATCH);
    proj_small_kernel<<<gproj, 256>>>(sk, Wq, bq, q_p);
    proj_small_kernel<<<gproj, 256>>>(ex, Wk, bk, k_p);

    // 2) v projection via 3xBF16 mma -> fp16
    dim3 gv(NDIM / 128, CDIM / 64, BATCH);
    proj_v_mma_kernel<<<gv, 256>>>(ex, Wv, bv, vh);

    // 3+4) fused energy (fp16 mma) + softmax -> normalized attn fp32 + fp16
    static int smem_set = 0;
    if (!smem_set) {
        cudaFuncSetAttribute(texture_mma_kernel,
                             cudaFuncAttributeMaxDynamicSharedMemorySize, XSMEM_BYTES);
        smem_set = 1;
    }
    dim3 ga(NDIM / 128, BATCH);
    attn_fused_kernel<<<ga, 256>>>(q_p, k_p, attn_p, ah);

    // 5) texture GEMM via fp16 mma, 32-wide K chunks, 4-stage pipeline
    dim3 gt(NDIM / 128, CDIM / 128, BATCH);
    texture_mma_kernel<<<gt, 256, XSMEM_BYTES>>>(vh, ah, sk, tex_p, out_p);
}

// round 14
// speedup vs baseline: 1.4504x; 1.4504x over previous
#include <cuda_runtime.h>
#include <cuda_bf16.h>
#include <cuda_fp16.h>
#include <math.h>
#include <stdint.h>

#define BATCH 8
#define CDIM  256
#define NDIM  4096
#define CQKD  32
#define ATT_SCALE 0.1767766952966369f   // 1/sqrt(32)

// ---------------- scratch (device globals) ------------------------------------
__device__ __half g_q[(size_t)BATCH * NDIM * CQKD];           // q fp16
__device__ __half g_k[(size_t)BATCH * NDIM * CQKD];           // k fp16
__device__ __half g_vh[(size_t)BATCH * CDIM * NDIM];          // V fp16
__device__ __half g_ah[(size_t)BATCH * NDIM * NDIM];          // attn fp16
__device__ float g_attn_fb[(size_t)BATCH * NDIM * NDIM];      // fallback
__device__ float g_tex_fb[(size_t)BATCH * CDIM * NDIM];       // fallback

// =============================== PTX helpers ==================================
__device__ __forceinline__ uint32_t smem_u32(const void* p) {
    uint32_t a;
    asm("{ .reg .u64 t; cvta.to.shared.u64 t, %1; cvt.u32.u64 %0, t; }"
        : "=r"(a) : "l"(p));
    return a;
}
__device__ __forceinline__ void cp16(uint32_t dst, const void* src) {
    asm volatile("cp.async.cg.shared.global [%0], [%1], 16;" :: "r"(dst), "l"(src) : "memory");
}
#define CP_COMMIT() asm volatile("cp.async.commit_group;" ::: "memory")
#define CP_WAIT1()  asm volatile("cp.async.wait_group 1;"  ::: "memory")
#define CP_WAIT2()  asm volatile("cp.async.wait_group 2;"  ::: "memory")
#define CP_WAIT0()  asm volatile("cp.async.wait_group 0;"  ::: "memory")

__device__ __forceinline__ void ldm_x4(uint32_t* r, uint32_t addr) {
    asm volatile("ldmatrix.sync.aligned.m8n8.x4.shared.b16 {%0,%1,%2,%3}, [%4];"
        : "=r"(r[0]), "=r"(r[1]), "=r"(r[2]), "=r"(r[3]) : "r"(addr));
}
__device__ __forceinline__ void ldm_x4_t(uint32_t* r, uint32_t addr) {
    asm volatile("ldmatrix.sync.aligned.m8n8.x4.trans.shared.b16 {%0,%1,%2,%3}, [%4];"
        : "=r"(r[0]), "=r"(r[1]), "=r"(r[2]), "=r"(r[3]) : "r"(addr));
}
__device__ __forceinline__ void mma_bf16(float* c, const uint32_t* a, const uint32_t* b) {
    asm volatile(
        "mma.sync.aligned.m16n8k16.row.col.f32.bf16.bf16.f32 "
        "{%0,%1,%2,%3}, {%4,%5,%6,%7}, {%8,%9}, {%0,%1,%2,%3};"
        : "+f"(c[0]), "+f"(c[1]), "+f"(c[2]), "+f"(c[3])
        : "r"(a[0]), "r"(a[1]), "r"(a[2]), "r"(a[3]), "r"(b[0]), "r"(b[1]));
}
__device__ __forceinline__ void mma_f16(float* c, const uint32_t* a, const uint32_t* b) {
    asm volatile(
        "mma.sync.aligned.m16n8k16.row.col.f32.f16.f16.f32 "
        "{%0,%1,%2,%3}, {%4,%5,%6,%7}, {%8,%9}, {%0,%1,%2,%3};"
        : "+f"(c[0]), "+f"(c[1]), "+f"(c[2]), "+f"(c[3])
        : "r"(a[0]), "r"(a[1]), "r"(a[2]), "r"(a[3]), "r"(b[0]), "r"(b[1]));
}
__device__ __forceinline__ uint32_t bfpack(float x, float y) {
    __nv_bfloat162 h = __floats2bfloat162_rn(x, y);
    return *(uint32_t*)&h;
}
__device__ __forceinline__ void split2(float x, float y, uint32_t& hi, uint32_t& lo) {
    __nv_bfloat16 hx = __float2bfloat16(x);
    __nv_bfloat16 hy = __float2bfloat16(y);
    float lx = x - __bfloat162float(hx);
    float ly = y - __bfloat162float(hy);
    __nv_bfloat162 hp; hp.x = hx; hp.y = hy;
    hi = *(uint32_t*)&hp;
    lo = bfpack(lx, ly);
}

// ---------------- q / k projection -> fp16 plane -------------------------------
__global__ void proj_small_kernel(const float* __restrict__ X,
                                  const float* __restrict__ W,
                                  const float* __restrict__ bias,
                                  __half* __restrict__ Y)
{
    __shared__ float Ws[CQKD * CDIM];
    int tid = threadIdx.x;
    for (int i = tid; i < CQKD * CDIM; i += 256) Ws[i] = W[i];
    __syncthreads();

    int b = blockIdx.y;
    int n = blockIdx.x * 256 + tid;
    const float* Xp = X + (size_t)b * CDIM * NDIM + n;

    float acc[CQKD];
#pragma unroll
    for (int o = 0; o < CQKD; o++) acc[o] = bias[o];

    for (int c = 0; c < CDIM; c++) {
        float x = Xp[(size_t)c * NDIM];
#pragma unroll
        for (int o = 0; o < CQKD; o++) acc[o] += x * Ws[o * CDIM + c];
    }
    size_t base = ((size_t)b * NDIM + n) * CQKD;
    uint32_t* ph = (uint32_t*)(Y + base);
#pragma unroll
    for (int o = 0; o < CQKD; o += 2) {
        __half2 h = __floats2half2_rn(acc[o], acc[o + 1]);
        ph[o >> 1] = *(uint32_t*)&h;
    }
}

// ============== proj_v via 3xBF16 mma: V[c,n] = Wv[c,:].X[:,n] + bv ============
#define PV_AP  5120
#define PV_XP  8704
#define PV_A_OFF  0
#define PV_X_OFF  (2 * PV_AP)
#define PV_SMEM   (PV_X_OFF + 2 * PV_XP)

__global__ void __launch_bounds__(256, 2)
proj_v_mma_kernel(const float* __restrict__ X,
                  const float* __restrict__ Wv,
                  const float* __restrict__ bv,
                  __half* __restrict__ VH)
{
    __shared__ __align__(16) char sm[PV_SMEM];
    uint32_t sb = smem_u32(sm);
    int tid = threadIdx.x;
    int wid = tid >> 5, lid = tid & 31;
    int g = lid >> 2, t = lid & 3;
    int wm = wid & 1, wn = wid >> 1;

    int b  = blockIdx.z;
    int m0 = blockIdx.y * 64;
    int n0 = blockIdx.x * 128;

    const float* Xb = X + (size_t)b * CDIM * NDIM;

    int am = tid >> 2, aq = tid & 3;
    int xk = tid >> 3, xq = (tid & 7) * 16;

    float4 wreg[2], xreg[4];
    {
        const float* wp = Wv + (size_t)(m0 + am) * CDIM + aq * 8;
        wreg[0] = *(const float4*)(wp);
        wreg[1] = *(const float4*)(wp + 4);
        const float* xp = Xb + (size_t)xk * NDIM + n0 + xq;
#pragma unroll
        for (int i = 0; i < 4; i++) xreg[i] = *(const float4*)(xp + i * 4);
    }

    float acc[2][4][4];
#pragma unroll
    for (int mt = 0; mt < 2; mt++)
#pragma unroll
        for (int nt = 0; nt < 4; nt++)
#pragma unroll
            for (int q = 0; q < 4; q++) acc[mt][nt][q] = 0.f;

    uint32_t a_lane = (uint32_t)(lid & 15) * 80 + (uint32_t)(lid >> 4) * 16;
    uint32_t bt_lane = (uint32_t)((lid & 7) + ((lid >> 3) & 1) * 8) * 272
                     + (uint32_t)(lid >> 4) * 16;

    for (int kc = 0; kc < 8; kc++) {
        {
            uint32_t ad = (uint32_t)PV_A_OFF + (uint32_t)am * 80 + aq * 16;
            float av[8] = {wreg[0].x, wreg[0].y, wreg[0].z, wreg[0].w,
                           wreg[1].x, wreg[1].y, wreg[1].z, wreg[1].w};
#pragma unroll
            for (int i = 0; i < 4; i++) {
                uint32_t hi, lo;
                split2(av[2 * i], av[2 * i + 1], hi, lo);
                *(uint32_t*)(sm + ad + i * 4) = hi;
                *(uint32_t*)(sm + ad + PV_AP + i * 4) = lo;
            }
            uint32_t xd = (uint32_t)PV_X_OFF + (uint32_t)xk * 272 + xq * 2;
            float xv[16] = {xreg[0].x, xreg[0].y, xreg[0].z, xreg[0].w,
                            xreg[1].x, xreg[1].y, xreg[1].z, xreg[1].w,
                            xreg[2].x, xreg[2].y, xreg[2].z, xreg[2].w,
                            xreg[3].x, xreg[3].y, xreg[3].z, xreg[3].w};
#pragma unroll
            for (int i = 0; i < 8; i++) {
                uint32_t hi, lo;
                split2(xv[2 * i], xv[2 * i + 1], hi, lo);
                *(uint32_t*)(sm + xd + i * 4) = hi;
                *(uint32_t*)(sm + xd + PV_XP + i * 4) = lo;
            }
        }
        __syncthreads();

        if (kc < 7) {
            const float* wp = Wv + (size_t)(m0 + am) * CDIM + (kc + 1) * 32 + aq * 8;
            wreg[0] = *(const float4*)(wp);
            wreg[1] = *(const float4*)(wp + 4);
            const float* xp = Xb + (size_t)((kc + 1) * 32 + xk) * NDIM + n0 + xq;
#pragma unroll
            for (int i = 0; i < 4; i++) xreg[i] = *(const float4*)(xp + i * 4);
        }

#pragma unroll
        for (int ks = 0; ks < 2; ks++) {
            uint32_t ah[2][4], al[2][4];
#pragma unroll
            for (int mt = 0; mt < 2; mt++) {
                uint32_t ro = (uint32_t)(wm * 32 + mt * 16) * 80 + ks * 32 + a_lane;
                ldm_x4(ah[mt], sb + PV_A_OFF + ro);
                ldm_x4(al[mt], sb + PV_A_OFF + PV_AP + ro);
            }
            uint32_t bh[2][4], bl[2][4];
#pragma unroll
            for (int p = 0; p < 2; p++) {
                uint32_t ro = (uint32_t)(ks * 16) * 272 + (uint32_t)(wn * 32 + p * 16) * 2 + bt_lane;
                ldm_x4_t(bh[p], sb + PV_X_OFF + ro);
                ldm_x4_t(bl[p], sb + PV_X_OFF + PV_XP + ro);
            }
#pragma unroll
            for (int mt = 0; mt < 2; mt++)
#pragma unroll
                for (int nt = 0; nt < 4; nt++) {
                    const uint32_t* bhp = &bh[nt >> 1][(nt & 1) * 2];
                    const uint32_t* blp = &bl[nt >> 1][(nt & 1) * 2];
                    mma_bf16(acc[mt][nt], ah[mt], bhp);
                    mma_bf16(acc[mt][nt], ah[mt], blp);
                    mma_bf16(acc[mt][nt], al[mt], bhp);
                }
        }
        __syncthreads();
    }

#pragma unroll
    for (int mt = 0; mt < 2; mt++) {
        int r0 = m0 + wm * 32 + mt * 16 + g;
        float b0 = bv[r0], b1 = bv[r0 + 8];
#pragma unroll
        for (int nt = 0; nt < 4; nt++) {
            int col = n0 + wn * 32 + nt * 8 + 2 * t;
            size_t off0 = ((size_t)b * CDIM + r0) * NDIM + col;
            size_t off1 = ((size_t)b * CDIM + r0 + 8) * NDIM + col;
            __half2 h0 = __floats2half2_rn(acc[mt][nt][0] + b0, acc[mt][nt][1] + b0);
            __half2 h1 = __floats2half2_rn(acc[mt][nt][2] + b1, acc[mt][nt][3] + b1);
            *(uint32_t*)(VH + off0) = *(uint32_t*)&h0;
            *(uint32_t*)(VH + off1) = *(uint32_t*)&h1;
        }
    }
}

// ======== fused energy + softmax via fp16 mma (no max; |E·scale| < ~1) ========
#define QPLANE 10240
#define KPLANE 5120
#define FK_K_OFF   QPLANE
#define FK_RS_OFF  (FK_K_OFF + 3 * KPLANE)
#define FK_INV_OFF (FK_RS_OFF + 128 * 4 * 4)
#define FK_SMEM    (FK_INV_OFF + 128 * 4)
#define FK_NCH (NDIM / 64)

__device__ __forceinline__ void fk_load_k(int j, uint32_t sb, int tid,
                                          const __half* Kb)
{
    uint32_t st = sb + FK_K_OFF + (uint32_t)(j % 3) * KPLANE;
    int row = tid >> 2;
    int q   = tid & 3;
    cp16(st + (uint32_t)row * 80 + q * 16,
         Kb + (size_t)(j * 64 + row) * CQKD + q * 8);
}

__global__ void __launch_bounds__(256, 2)
attn_fused_kernel(const __half* __restrict__ Q,
                  const __half* __restrict__ K,
                  float* __restrict__ A,
                  __half* __restrict__ AH)
{
    __shared__ __align__(16) char smem[FK_SMEM];
    uint32_t sb = smem_u32(smem);
    float* rs  = (float*)(smem + FK_RS_OFF);
    float* inv = (float*)(smem + FK_INV_OFF);

    int tid = threadIdx.x;
    int wid = tid >> 5, lid = tid & 31;
    int g = lid >> 2, t = lid & 3;
    int wm = wid & 1, wn = wid >> 1;

    int b  = blockIdx.y;
    int m0 = blockIdx.x * 128;

    const __half* Kb = K + (size_t)b * NDIM * CQKD;

    {
        int row  = tid >> 1;
        int half = tid & 1;
        const __half* s0 = Q + ((size_t)b * NDIM + m0 + row) * CQKD + half * 16;
        uint32_t d = sb + (uint32_t)row * 80 + half * 32;
        cp16(d, s0); cp16(d + 16, s0 + 8);
    }

    uint32_t a_lane = (uint32_t)(lid & 15) * 80 + (uint32_t)(lid >> 4) * 16;
    uint32_t b_lane = (uint32_t)((lid & 7) + (lid >> 4) * 8) * 80
                    + (uint32_t)((lid >> 3) & 1) * 16;

    float rsum0[4] = {0.f, 0.f, 0.f, 0.f};
    float rsum1[4] = {0.f, 0.f, 0.f, 0.f};

    for (int pass = 0; pass < 2; pass++) {
        fk_load_k(0, sb, tid, Kb); CP_COMMIT();
        fk_load_k(1, sb, tid, Kb); CP_COMMIT();

        for (int j = 0; j < FK_NCH; j++) {
            CP_WAIT1();
            __syncthreads();

            uint32_t kst = sb + FK_K_OFF + (uint32_t)(j % 3) * KPLANE;
            float acc[4][2][4];
#pragma unroll
            for (int mt = 0; mt < 4; mt++)
#pragma unroll
                for (int nt = 0; nt < 2; nt++)
#pragma unroll
                    for (int q = 0; q < 4; q++) acc[mt][nt][q] = 0.f;

#pragma unroll
            for (int ks = 0; ks < 2; ks++) {
                uint32_t af[4][4];
#pragma unroll
                for (int mt = 0; mt < 4; mt++)
                    ldm_x4(af[mt], sb + (uint32_t)(wm * 64 + mt * 16) * 80 + ks * 32 + a_lane);
                uint32_t bf[4];
                ldm_x4(bf, kst + (uint32_t)(wn * 16) * 80 + ks * 32 + b_lane);
#pragma unroll
                for (int mt = 0; mt < 4; mt++)
#pragma unroll
                    for (int nt = 0; nt < 2; nt++)
                        mma_f16(acc[mt][nt], af[mt], &bf[nt * 2]);
            }
            __syncthreads();
            if (j + 2 < FK_NCH) fk_load_k(j + 2, sb, tid, Kb);
            CP_COMMIT();

            if (pass == 0) {
#pragma unroll
                for (int mt = 0; mt < 4; mt++) {
                    float s0 = 0.f, s1 = 0.f;
#pragma unroll
                    for (int nt = 0; nt < 2; nt++) {
                        s0 += __expf(acc[mt][nt][0] * ATT_SCALE) + __expf(acc[mt][nt][1] * ATT_SCALE);
                        s1 += __expf(acc[mt][nt][2] * ATT_SCALE) + __expf(acc[mt][nt][3] * ATT_SCALE);
                    }
                    s0 += __shfl_xor_sync(0xffffffffu, s0, 1);
                    s0 += __shfl_xor_sync(0xffffffffu, s0, 2);
                    s1 += __shfl_xor_sync(0xffffffffu, s1, 1);
                    s1 += __shfl_xor_sync(0xffffffffu, s1, 2);
                    rsum0[mt] += s0;
                    rsum1[mt] += s1;
                }
            } else {
#pragma unroll
                for (int mt = 0; mt < 4; mt++) {
                    int r0 = m0 + wm * 64 + mt * 16 + g;
                    float i0 = inv[wm * 64 + mt * 16 + g];
                    float i1 = inv[wm * 64 + mt * 16 + g + 8];
#pragma unroll
                    for (int nt = 0; nt < 2; nt++) {
                        int col = j * 64 + wn * 16 + nt * 8 + 2 * t;
                        float p0 = __expf(acc[mt][nt][0] * ATT_SCALE) * i0;
                        float p1 = __expf(acc[mt][nt][1] * ATT_SCALE) * i0;
                        float p2 = __expf(acc[mt][nt][2] * ATT_SCALE) * i1;
                        float p3 = __expf(acc[mt][nt][3] * ATT_SCALE) * i1;
                        size_t off0 = ((size_t)b * NDIM + r0) * NDIM + col;
                        size_t off1 = ((size_t)b * NDIM + r0 + 8) * NDIM + col;
                        float2 f0 = {p0, p1};
                        float2 f1 = {p2, p3};
                        *(float2*)(A + off0) = f0;
                        *(float2*)(A + off1) = f1;
                        __half2 h0 = __floats2half2_rn(p0, p1);
                        __half2 h1 = __floats2half2_rn(p2, p3);
                        *(uint32_t*)(AH + off0) = *(uint32_t*)&h0;
                        *(uint32_t*)(AH + off1) = *(uint32_t*)&h1;
                    }
                }
            }
        }

        if (pass == 0) {
            CP_WAIT0();
            __syncthreads();
            if (t == 0) {
#pragma unroll
                for (int mt = 0; mt < 4; mt++) {
                    rs[(wm * 64 + mt * 16 + g) * 4 + wn]     = rsum0[mt];
                    rs[(wm * 64 + mt * 16 + g + 8) * 4 + wn] = rsum1[mt];
                }
            }
            __syncthreads();
            if (tid < 128)
                inv[tid] = 1.0f / (rs[tid * 4] + rs[tid * 4 + 1] + rs[tid * 4 + 2] + rs[tid * 4 + 3]);
            __syncthreads();
        }
    }
}

// ============== texture GEMM via fp16 mma, K-chunks of 32, 4-stage =============
// tex[b,c,m] = sum_n V[b,c,n] * attn[b,m,n];  out = tex + sketches
#define EPLANE 10240                    // 128 rows x 80B
#define XSTAGE_BYTES (2 * EPLANE)       // V plane + A plane -> 20480
#define XSTAGES 4
#define XSMEM_BYTES (XSTAGES * XSTAGE_BYTES)   // 81920
#define XNCH (NDIM / 32)                // 128

__device__ __forceinline__ void x_load_chunk(int j, uint32_t sb_base, int tid,
                                             const __half* VHb, const __half* AHb)
{
    uint32_t sb = sb_base + (uint32_t)(j & (XSTAGES - 1)) * XSTAGE_BYTES;
    int row  = tid >> 1;
    int half = tid & 1;
    int kt = j * 32;

    const __half* s0 = VHb + (size_t)row * NDIM + kt + half * 16;
    const __half* s1 = AHb + (size_t)row * NDIM + kt + half * 16;
    uint32_t d0 = sb + (uint32_t)row * 80 + half * 32;
    uint32_t d1 = d0 + EPLANE;
    cp16(d0, s0); cp16(d0 + 16, s0 + 8);
    cp16(d1, s1); cp16(d1 + 16, s1 + 8);
}

__global__ void __launch_bounds__(256, 2)
texture_mma_kernel(const __half* __restrict__ VH,
                   const __half* __restrict__ AH,
                   const float* __restrict__ SK,
                   float* __restrict__ TEX,
                   float* __restrict__ OUT)
{
    extern __shared__ char smem[];
    uint32_t sb_base = smem_u32(smem);
    int tid = threadIdx.x;
    int wid = tid >> 5, lid = tid & 31;
    int g = lid >> 2, t = lid & 3;
    int wm = wid & 1, wn = wid >> 1;

    int b  = blockIdx.z;
    int i0 = blockIdx.y * 128;
    int j0 = blockIdx.x * 128;

    const __half* VHb = VH + ((size_t)b * CDIM + i0) * NDIM;
    const __half* AHb = AH + ((size_t)b * NDIM + j0) * NDIM;

    float acc[4][4][4];
#pragma unroll
    for (int mt = 0; mt < 4; mt++)
#pragma unroll
        for (int nt = 0; nt < 4; nt++)
#pragma unroll
            for (int q = 0; q < 4; q++) acc[mt][nt][q] = 0.f;

    x_load_chunk(0, sb_base, tid, VHb, AHb); CP_COMMIT();
    x_load_chunk(1, sb_base, tid, VHb, AHb); CP_COMMIT();
    x_load_chunk(2, sb_base, tid, VHb, AHb); CP_COMMIT();

    uint32_t a_lane = (uint32_t)(lid & 15) * 80 + (uint32_t)(lid >> 4) * 16;
    uint32_t b_lane = (uint32_t)((lid & 7) + ((lid >> 4) * 8)) * 80
                    + (uint32_t)((lid >> 3) & 1) * 16;

    for (int i = 0; i < XNCH; i++) {
        CP_WAIT2();
        __syncthreads();
        if (i + 3 < XNCH) x_load_chunk(i + 3, sb_base, tid, VHb, AHb);
        CP_COMMIT();

        uint32_t sA = sb_base + (uint32_t)(i & (XSTAGES - 1)) * XSTAGE_BYTES;
        uint32_t sB = sA + EPLANE;

#pragma unroll
        for (int ks = 0; ks < 2; ks++) {
            uint32_t af[4][4];
#pragma unroll
            for (int mt = 0; mt < 4; mt++)
                ldm_x4(af[mt], sA + (uint32_t)(wm * 64 + mt * 16) * 80 + ks * 32 + a_lane);
            uint32_t bq[2][4];
#pragma unroll
            for (int p = 0; p < 2; p++)
                ldm_x4(bq[p], sB + (uint32_t)(wn * 32 + p * 16) * 80 + ks * 32 + b_lane);
#pragma unroll
            for (int mt = 0; mt < 4; mt++)
#pragma unroll
                for (int nt = 0; nt < 4; nt++)
                    mma_f16(acc[mt][nt], af[mt], &bq[nt >> 1][(nt & 1) * 2]);
        }
        __syncthreads();
    }
    CP_WAIT0();

#pragma unroll
    for (int mt = 0; mt < 4; mt++) {
        int r0 = i0 + wm * 64 + mt * 16 + g;
#pragma unroll
        for (int nt = 0; nt < 4; nt++) {
            int col = j0 + wn * 32 + nt * 8 + 2 * t;
            size_t off0 = ((size_t)b * CDIM + r0) * NDIM + col;
            size_t off1 = ((size_t)b * CDIM + r0 + 8) * NDIM + col;
            float2 t0 = {acc[mt][nt][0], acc[mt][nt][1]};
            float2 t1 = {acc[mt][nt][2], acc[mt][nt][3]};
            float2 s0 = *(const float2*)(SK + off0);
            float2 s1 = *(const float2*)(SK + off1);
            *(float2*)(TEX + off0) = t0;
            *(float2*)(TEX + off1) = t1;
            float2 o0 = {t0.x + s0.x, t0.y + s0.y};
            float2 o1 = {t1.x + s1.x, t1.y + s1.y};
            *(float2*)(OUT + off0) = o0;
            *(float2*)(OUT + off1) = o1;
        }
    }
}

// ---------------- launch -------------------------------------------------------
extern "C" void kernel_launch(void* const* d_in, const int* in_sizes, int n_in,
                              void* d_out, int out_size)
{
    const float* sk = (const float*)d_in[0];
    const float* ex = (const float*)d_in[1];
    const float* Wq = (const float*)d_in[2];
    const float* bq = (const float*)d_in[3];
    const float* Wk = (const float*)d_in[4];
    const float* bk = (const float*)d_in[5];
    const float* Wv = (const float*)d_in[6];
    const float* bv = (const float*)d_in[7];

    const size_t BCN = (size_t)BATCH * CDIM * NDIM;
    const size_t BNN = (size_t)BATCH * NDIM * NDIM;

    float* out_p = (float*)d_out;
    float* tex_p;
    float* attn_p;

    if ((size_t)(unsigned)out_size >= 2 * BCN + BNN) {
        tex_p  = out_p + BCN;
        attn_p = out_p + 2 * BCN;
    } else {
        void* p;
        cudaGetSymbolAddress(&p, g_tex_fb);  tex_p  = (float*)p;
        cudaGetSymbolAddress(&p, g_attn_fb); attn_p = (float*)p;
    }

    __half *q_p, *k_p, *vh, *ah;
    { void* p;
      cudaGetSymbolAddress(&p, g_q);  q_p = (__half*)p;
      cudaGetSymbolAddress(&p, g_k);  k_p = (__half*)p;
      cudaGetSymbolAddress(&p, g_vh); vh  = (__half*)p;
      cudaGetSymbolAddress(&p, g_ah); ah  = (__half*)p; }

    // 1) q, k projections -> fp16
    dim3 gproj(NDIM / 256, BATCH);
    proj_small_kernel<<<gproj, 256>>>(sk, Wq, bq, q_p);
    proj_small_kernel<<<gproj, 256>>>(ex, Wk, bk, k_p);

    // 2) v projection via 3xBF16 mma -> fp16
    dim3 gv(NDIM / 128, CDIM / 64, BATCH);
    proj_v_mma_kernel<<<gv, 256>>>(ex, Wv, bv, vh);

    // 3+4) fused energy (fp16 mma) + softmax -> normalized attn fp32 + fp16
    static int smem_set = 0;
    if (!smem_set) {
        cudaFuncSetAttribute(texture_mma_kernel,
                             cudaFuncAttributeMaxDynamicSharedMemorySize, XSMEM_BYTES);
        smem_set = 1;
    }
    dim3 ga(NDIM / 128, BATCH);
    attn_fused_kernel<<<ga, 256>>>(q_p, k_p, attn_p, ah);

    // 5) texture GEMM via fp16 mma, 32-wide K chunks, 4-stage pipeline
    dim3 gt(NDIM / 128, CDIM / 128, BATCH);
    texture_mma_kernel<<<gt, 256, XSMEM_BYTES>>>(vh, ah, sk, tex_p, out_p);
}

// round 15
// speedup vs baseline: 1.7464x; 1.2041x over previous
#include <cuda_runtime.h>
#include <cuda_bf16.h>
#include <cuda_fp16.h>
#include <math.h>
#include <stdint.h>

#define BATCH 8
#define CDIM  256
#define NDIM  4096
#define CQKD  32
#define ATT_SCALE 0.1767766952966369f   // 1/sqrt(32)

// ---------------- scratch (device globals) ------------------------------------
__device__ __half g_q[(size_t)BATCH * NDIM * CQKD];           // q fp16
__device__ __half g_k[(size_t)BATCH * NDIM * CQKD];           // k fp16
__device__ __half g_vh[(size_t)BATCH * CDIM * NDIM];          // V fp16
__device__ __half g_ah[(size_t)BATCH * NDIM * NDIM];          // attn fp16
__device__ float g_attn_fb[(size_t)BATCH * NDIM * NDIM];      // fallback
__device__ float g_tex_fb[(size_t)BATCH * CDIM * NDIM];       // fallback

// =============================== PTX helpers ==================================
__device__ __forceinline__ uint32_t smem_u32(const void* p) {
    uint32_t a;
    asm("{ .reg .u64 t; cvta.to.shared.u64 t, %1; cvt.u32.u64 %0, t; }"
        : "=r"(a) : "l"(p));
    return a;
}
__device__ __forceinline__ void cp16(uint32_t dst, const void* src) {
    asm volatile("cp.async.cg.shared.global [%0], [%1], 16;" :: "r"(dst), "l"(src) : "memory");
}
#define CP_COMMIT() asm volatile("cp.async.commit_group;" ::: "memory")
#define CP_WAIT1()  asm volatile("cp.async.wait_group 1;"  ::: "memory")
#define CP_WAIT2()  asm volatile("cp.async.wait_group 2;"  ::: "memory")
#define CP_WAIT0()  asm volatile("cp.async.wait_group 0;"  ::: "memory")

__device__ __forceinline__ void ldm_x4(uint32_t* r, uint32_t addr) {
    asm volatile("ldmatrix.sync.aligned.m8n8.x4.shared.b16 {%0,%1,%2,%3}, [%4];"
        : "=r"(r[0]), "=r"(r[1]), "=r"(r[2]), "=r"(r[3]) : "r"(addr));
}
__device__ __forceinline__ void ldm_x4_t(uint32_t* r, uint32_t addr) {
    asm volatile("ldmatrix.sync.aligned.m8n8.x4.trans.shared.b16 {%0,%1,%2,%3}, [%4];"
        : "=r"(r[0]), "=r"(r[1]), "=r"(r[2]), "=r"(r[3]) : "r"(addr));
}
__device__ __forceinline__ void mma_bf16(float* c, const uint32_t* a, const uint32_t* b) {
    asm volatile(
        "mma.sync.aligned.m16n8k16.row.col.f32.bf16.bf16.f32 "
        "{%0,%1,%2,%3}, {%4,%5,%6,%7}, {%8,%9}, {%0,%1,%2,%3};"
        : "+f"(c[0]), "+f"(c[1]), "+f"(c[2]), "+f"(c[3])
        : "r"(a[0]), "r"(a[1]), "r"(a[2]), "r"(a[3]), "r"(b[0]), "r"(b[1]));
}
__device__ __forceinline__ void mma_f16(float* c, const uint32_t* a, const uint32_t* b) {
    asm volatile(
        "mma.sync.aligned.m16n8k16.row.col.f32.f16.f16.f32 "
        "{%0,%1,%2,%3}, {%4,%5,%6,%7}, {%8,%9}, {%0,%1,%2,%3};"
        : "+f"(c[0]), "+f"(c[1]), "+f"(c[2]), "+f"(c[3])
        : "r"(a[0]), "r"(a[1]), "r"(a[2]), "r"(a[3]), "r"(b[0]), "r"(b[1]));
}
__device__ __forceinline__ uint32_t bfpack(float x, float y) {
    __nv_bfloat162 h = __floats2bfloat162_rn(x, y);
    return *(uint32_t*)&h;
}
__device__ __forceinline__ void split2(float x, float y, uint32_t& hi, uint32_t& lo) {
    __nv_bfloat16 hx = __float2bfloat16(x);
    __nv_bfloat16 hy = __float2bfloat16(y);
    float lx = x - __bfloat162float(hx);
    float ly = y - __bfloat162float(hy);
    __nv_bfloat162 hp; hp.x = hx; hp.y = hy;
    hi = *(uint32_t*)&hp;
    lo = bfpack(lx, ly);
}

// ---------------- q / k projection -> fp16 plane -------------------------------
__global__ void proj_small_kernel(const float* __restrict__ X,
                                  const float* __restrict__ W,
                                  const float* __restrict__ bias,
                                  __half* __restrict__ Y)
{
    __shared__ float Ws[CQKD * CDIM];
    int tid = threadIdx.x;
    for (int i = tid; i < CQKD * CDIM; i += 256) Ws[i] = W[i];
    __syncthreads();

    int b = blockIdx.y;
    int n = blockIdx.x * 256 + tid;
    const float* Xp = X + (size_t)b * CDIM * NDIM + n;

    float acc[CQKD];
#pragma unroll
    for (int o = 0; o < CQKD; o++) acc[o] = bias[o];

    for (int c = 0; c < CDIM; c++) {
        float x = Xp[(size_t)c * NDIM];
#pragma unroll
        for (int o = 0; o < CQKD; o++) acc[o] += x * Ws[o * CDIM + c];
    }
    size_t base = ((size_t)b * NDIM + n) * CQKD;
    uint32_t* ph = (uint32_t*)(Y + base);
#pragma unroll
    for (int o = 0; o < CQKD; o += 2) {
        __half2 h = __floats2half2_rn(acc[o], acc[o + 1]);
        ph[o >> 1] = *(uint32_t*)&h;
    }
}

// ============== proj_v via 3xBF16 mma: V[c,n] = Wv[c,:].X[:,n] + bv ============
#define PV_AP  5120
#define PV_XP  8704
#define PV_A_OFF  0
#define PV_X_OFF  (2 * PV_AP)
#define PV_SMEM   (PV_X_OFF + 2 * PV_XP)

__global__ void __launch_bounds__(256, 2)
proj_v_mma_kernel(const float* __restrict__ X,
                  const float* __restrict__ Wv,
                  const float* __restrict__ bv,
                  __half* __restrict__ VH)
{
    __shared__ __align__(16) char sm[PV_SMEM];
    uint32_t sb = smem_u32(sm);
    int tid = threadIdx.x;
    int wid = tid >> 5, lid = tid & 31;
    int g = lid >> 2, t = lid & 3;
    int wm = wid & 1, wn = wid >> 1;

    int b  = blockIdx.z;
    int m0 = blockIdx.y * 64;
    int n0 = blockIdx.x * 128;

    const float* Xb = X + (size_t)b * CDIM * NDIM;

    int am = tid >> 2, aq = tid & 3;
    int xk = tid >> 3, xq = (tid & 7) * 16;

    float4 wreg[2], xreg[4];
    {
        const float* wp = Wv + (size_t)(m0 + am) * CDIM + aq * 8;
        wreg[0] = *(const float4*)(wp);
        wreg[1] = *(const float4*)(wp + 4);
        const float* xp = Xb + (size_t)xk * NDIM + n0 + xq;
#pragma unroll
        for (int i = 0; i < 4; i++) xreg[i] = *(const float4*)(xp + i * 4);
    }

    float acc[2][4][4];
#pragma unroll
    for (int mt = 0; mt < 2; mt++)
#pragma unroll
        for (int nt = 0; nt < 4; nt++)
#pragma unroll
            for (int q = 0; q < 4; q++) acc[mt][nt][q] = 0.f;

    uint32_t a_lane = (uint32_t)(lid & 15) * 80 + (uint32_t)(lid >> 4) * 16;
    uint32_t bt_lane = (uint32_t)((lid & 7) + ((lid >> 3) & 1) * 8) * 272
                     + (uint32_t)(lid >> 4) * 16;

    for (int kc = 0; kc < 8; kc++) {
        {
            uint32_t ad = (uint32_t)PV_A_OFF + (uint32_t)am * 80 + aq * 16;
            float av[8] = {wreg[0].x, wreg[0].y, wreg[0].z, wreg[0].w,
                           wreg[1].x, wreg[1].y, wreg[1].z, wreg[1].w};
#pragma unroll
            for (int i = 0; i < 4; i++) {
                uint32_t hi, lo;
                split2(av[2 * i], av[2 * i + 1], hi, lo);
                *(uint32_t*)(sm + ad + i * 4) = hi;
                *(uint32_t*)(sm + ad + PV_AP + i * 4) = lo;
            }
            uint32_t xd = (uint32_t)PV_X_OFF + (uint32_t)xk * 272 + xq * 2;
            float xv[16] = {xreg[0].x, xreg[0].y, xreg[0].z, xreg[0].w,
                            xreg[1].x, xreg[1].y, xreg[1].z, xreg[1].w,
                            xreg[2].x, xreg[2].y, xreg[2].z, xreg[2].w,
                            xreg[3].x, xreg[3].y, xreg[3].z, xreg[3].w};
#pragma unroll
            for (int i = 0; i < 8; i++) {
                uint32_t hi, lo;
                split2(xv[2 * i], xv[2 * i + 1], hi, lo);
                *(uint32_t*)(sm + xd + i * 4) = hi;
                *(uint32_t*)(sm + xd + PV_XP + i * 4) = lo;
            }
        }
        __syncthreads();

        if (kc < 7) {
            const float* wp = Wv + (size_t)(m0 + am) * CDIM + (kc + 1) * 32 + aq * 8;
            wreg[0] = *(const float4*)(wp);
            wreg[1] = *(const float4*)(wp + 4);
            const float* xp = Xb + (size_t)((kc + 1) * 32 + xk) * NDIM + n0 + xq;
#pragma unroll
            for (int i = 0; i < 4; i++) xreg[i] = *(const float4*)(xp + i * 4);
        }

#pragma unroll
        for (int ks = 0; ks < 2; ks++) {
            uint32_t ah[2][4], al[2][4];
#pragma unroll
            for (int mt = 0; mt < 2; mt++) {
                uint32_t ro = (uint32_t)(wm * 32 + mt * 16) * 80 + ks * 32 + a_lane;
                ldm_x4(ah[mt], sb + PV_A_OFF + ro);
                ldm_x4(al[mt], sb + PV_A_OFF + PV_AP + ro);
            }
            uint32_t bh[2][4], bl[2][4];
#pragma unroll
            for (int p = 0; p < 2; p++) {
                uint32_t ro = (uint32_t)(ks * 16) * 272 + (uint32_t)(wn * 32 + p * 16) * 2 + bt_lane;
                ldm_x4_t(bh[p], sb + PV_X_OFF + ro);
                ldm_x4_t(bl[p], sb + PV_X_OFF + PV_XP + ro);
            }
#pragma unroll
            for (int mt = 0; mt < 2; mt++)
#pragma unroll
                for (int nt = 0; nt < 4; nt++) {
                    const uint32_t* bhp = &bh[nt >> 1][(nt & 1) * 2];
                    const uint32_t* blp = &bl[nt >> 1][(nt & 1) * 2];
                    mma_bf16(acc[mt][nt], ah[mt], bhp);
                    mma_bf16(acc[mt][nt], ah[mt], blp);
                    mma_bf16(acc[mt][nt], al[mt], bhp);
                }
        }
        __syncthreads();
    }

#pragma unroll
    for (int mt = 0; mt < 2; mt++) {
        int r0 = m0 + wm * 32 + mt * 16 + g;
        float b0 = bv[r0], b1 = bv[r0 + 8];
#pragma unroll
        for (int nt = 0; nt < 4; nt++) {
            int col = n0 + wn * 32 + nt * 8 + 2 * t;
            size_t off0 = ((size_t)b * CDIM + r0) * NDIM + col;
            size_t off1 = ((size_t)b * CDIM + r0 + 8) * NDIM + col;
            __half2 h0 = __floats2half2_rn(acc[mt][nt][0] + b0, acc[mt][nt][1] + b0);
            __half2 h1 = __floats2half2_rn(acc[mt][nt][2] + b1, acc[mt][nt][3] + b1);
            *(uint32_t*)(VH + off0) = *(uint32_t*)&h0;
            *(uint32_t*)(VH + off1) = *(uint32_t*)&h1;
        }
    }
}

// ======== fused energy + softmax via fp16 mma (no max; |E·scale| < ~1) ========
#define QPLANE 10240
#define KPLANE 5120
#define FK_K_OFF   QPLANE
#define FK_RS_OFF  (FK_K_OFF + 3 * KPLANE)
#define FK_INV_OFF (FK_RS_OFF + 128 * 4 * 4)
#define FK_SMEM    (FK_INV_OFF + 128 * 4)
#define FK_NCH (NDIM / 64)

__device__ __forceinline__ void fk_load_k(int j, uint32_t sb, int tid,
                                          const __half* Kb)
{
    uint32_t st = sb + FK_K_OFF + (uint32_t)(j % 3) * KPLANE;
    int row = tid >> 2;
    int q   = tid & 3;
    cp16(st + (uint32_t)row * 80 + q * 16,
         Kb + (size_t)(j * 64 + row) * CQKD + q * 8);
}

__global__ void __launch_bounds__(256, 2)
attn_fused_kernel(const __half* __restrict__ Q,
                  const __half* __restrict__ K,
                  float* __restrict__ A,
                  __half* __restrict__ AH)
{
    __shared__ __align__(16) char smem[FK_SMEM];
    uint32_t sb = smem_u32(smem);
    float* rs  = (float*)(smem + FK_RS_OFF);
    float* inv = (float*)(smem + FK_INV_OFF);

    int tid = threadIdx.x;
    int wid = tid >> 5, lid = tid & 31;
    int g = lid >> 2, t = lid & 3;
    int wm = wid & 1, wn = wid >> 1;

    int b  = blockIdx.y;
    int m0 = blockIdx.x * 128;

    const __half* Kb = K + (size_t)b * NDIM * CQKD;

    {
        int row  = tid >> 1;
        int half = tid & 1;
        const __half* s0 = Q + ((size_t)b * NDIM + m0 + row) * CQKD + half * 16;
        uint32_t d = sb + (uint32_t)row * 80 + half * 32;
        cp16(d, s0); cp16(d + 16, s0 + 8);
    }

    uint32_t a_lane = (uint32_t)(lid & 15) * 80 + (uint32_t)(lid >> 4) * 16;
    uint32_t b_lane = (uint32_t)((lid & 7) + (lid >> 4) * 8) * 80
                    + (uint32_t)((lid >> 3) & 1) * 16;

    float rsum0[4] = {0.f, 0.f, 0.f, 0.f};
    float rsum1[4] = {0.f, 0.f, 0.f, 0.f};

    for (int pass = 0; pass < 2; pass++) {
        fk_load_k(0, sb, tid, Kb); CP_COMMIT();
        fk_load_k(1, sb, tid, Kb); CP_COMMIT();

        for (int j = 0; j < FK_NCH; j++) {
            CP_WAIT1();
            __syncthreads();

            uint32_t kst = sb + FK_K_OFF + (uint32_t)(j % 3) * KPLANE;
            float acc[4][2][4];
#pragma unroll
            for (int mt = 0; mt < 4; mt++)
#pragma unroll
                for (int nt = 0; nt < 2; nt++)
#pragma unroll
                    for (int q = 0; q < 4; q++) acc[mt][nt][q] = 0.f;

#pragma unroll
            for (int ks = 0; ks < 2; ks++) {
                uint32_t af[4][4];
#pragma unroll
                for (int mt = 0; mt < 4; mt++)
                    ldm_x4(af[mt], sb + (uint32_t)(wm * 64 + mt * 16) * 80 + ks * 32 + a_lane);
                uint32_t bf[4];
                ldm_x4(bf, kst + (uint32_t)(wn * 16) * 80 + ks * 32 + b_lane);
#pragma unroll
                for (int mt = 0; mt < 4; mt++)
#pragma unroll
                    for (int nt = 0; nt < 2; nt++)
                        mma_f16(acc[mt][nt], af[mt], &bf[nt * 2]);
            }
            __syncthreads();
            if (j + 2 < FK_NCH) fk_load_k(j + 2, sb, tid, Kb);
            CP_COMMIT();

            if (pass == 0) {
#pragma unroll
                for (int mt = 0; mt < 4; mt++) {
                    float s0 = 0.f, s1 = 0.f;
#pragma unroll
                    for (int nt = 0; nt < 2; nt++) {
                        s0 += __expf(acc[mt][nt][0] * ATT_SCALE) + __expf(acc[mt][nt][1] * ATT_SCALE);
                        s1 += __expf(acc[mt][nt][2] * ATT_SCALE) + __expf(acc[mt][nt][3] * ATT_SCALE);
                    }
                    s0 += __shfl_xor_sync(0xffffffffu, s0, 1);
                    s0 += __shfl_xor_sync(0xffffffffu, s0, 2);
                    s1 += __shfl_xor_sync(0xffffffffu, s1, 1);
                    s1 += __shfl_xor_sync(0xffffffffu, s1, 2);
                    rsum0[mt] += s0;
                    rsum1[mt] += s1;
                }
            } else {
#pragma unroll
                for (int mt = 0; mt < 4; mt++) {
                    int r0 = m0 + wm * 64 + mt * 16 + g;
                    float i0 = inv[wm * 64 + mt * 16 + g];
                    float i1 = inv[wm * 64 + mt * 16 + g + 8];
#pragma unroll
                    for (int nt = 0; nt < 2; nt++) {
                        int col = j * 64 + wn * 16 + nt * 8 + 2 * t;
                        float p0 = __expf(acc[mt][nt][0] * ATT_SCALE) * i0;
                        float p1 = __expf(acc[mt][nt][1] * ATT_SCALE) * i0;
                        float p2 = __expf(acc[mt][nt][2] * ATT_SCALE) * i1;
                        float p3 = __expf(acc[mt][nt][3] * ATT_SCALE) * i1;
                        size_t off0 = ((size_t)b * NDIM + r0) * NDIM + col;
                        size_t off1 = ((size_t)b * NDIM + r0 + 8) * NDIM + col;
                        float2 f0 = {p0, p1};
                        float2 f1 = {p2, p3};
                        *(float2*)(A + off0) = f0;
                        *(float2*)(A + off1) = f1;
                        __half2 h0 = __floats2half2_rn(p0, p1);
                        __half2 h1 = __floats2half2_rn(p2, p3);
                        *(uint32_t*)(AH + off0) = *(uint32_t*)&h0;
                        *(uint32_t*)(AH + off1) = *(uint32_t*)&h1;
                    }
                }
            }
        }

        if (pass == 0) {
            CP_WAIT0();
            __syncthreads();
            if (t == 0) {
#pragma unroll
                for (int mt = 0; mt < 4; mt++) {
                    rs[(wm * 64 + mt * 16 + g) * 4 + wn]     = rsum0[mt];
                    rs[(wm * 64 + mt * 16 + g + 8) * 4 + wn] = rsum1[mt];
                }
            }
            __syncthreads();
            if (tid < 128)
                inv[tid] = 1.0f / (rs[tid * 4] + rs[tid * 4 + 1] + rs[tid * 4 + 2] + rs[tid * 4 + 3]);
            __syncthreads();
        }
    }
}

// ============== texture GEMM via fp16 mma, K-chunks of 32, 4-stage =============
#define EPLANE 10240                    // 128 rows x 80B
#define XSTAGE_BYTES (2 * EPLANE)       // V plane + A plane -> 20480
#define XSTAGES 4
#define XSMEM_BYTES (XSTAGES * XSTAGE_BYTES)   // 81920
#define XNCH (NDIM / 32)                // 128

__device__ __forceinline__ void x_load_chunk(int j, uint32_t sb_base, int tid,
                                             const __half* VHb, const __half* AHb)
{
    uint32_t sb = sb_base + (uint32_t)(j & (XSTAGES - 1)) * XSTAGE_BYTES;
    int row  = tid >> 1;
    int half = tid & 1;
    int kt = j * 32;

    const __half* s0 = VHb + (size_t)row * NDIM + kt + half * 16;
    const __half* s1 = AHb + (size_t)row * NDIM + kt + half * 16;
    uint32_t d0 = sb + (uint32_t)row * 80 + half * 32;
    uint32_t d1 = d0 + EPLANE;
    cp16(d0, s0); cp16(d0 + 16, s0 + 8);
    cp16(d1, s1); cp16(d1 + 16, s1 + 8);
}

__global__ void __launch_bounds__(256, 2)
texture_mma_kernel(const __half* __restrict__ VH,
                   const __half* __restrict__ AH,
                   const float* __restrict__ SK,
                   float* __restrict__ TEX,
                   float* __restrict__ OUT)
{
    extern __shared__ char smem[];
    uint32_t sb_base = smem_u32(smem);
    int tid = threadIdx.x;
    int wid = tid >> 5, lid = tid & 31;
    int g = lid >> 2, t = lid & 3;
    int wm = wid & 1, wn = wid >> 1;

    int b  = blockIdx.z;
    int i0 = blockIdx.y * 128;
    int j0 = blockIdx.x * 128;

    const __half* VHb = VH + ((size_t)b * CDIM + i0) * NDIM;
    const __half* AHb = AH + ((size_t)b * NDIM + j0) * NDIM;

    float acc[4][4][4];
#pragma unroll
    for (int mt = 0; mt < 4; mt++)
#pragma unroll
        for (int nt = 0; nt < 4; nt++)
#pragma unroll
            for (int q = 0; q < 4; q++) acc[mt][nt][q] = 0.f;

    x_load_chunk(0, sb_base, tid, VHb, AHb); CP_COMMIT();
    x_load_chunk(1, sb_base, tid, VHb, AHb); CP_COMMIT();
    x_load_chunk(2, sb_base, tid, VHb, AHb); CP_COMMIT();

    uint32_t a_lane = (uint32_t)(lid & 15) * 80 + (uint32_t)(lid >> 4) * 16;
    uint32_t b_lane = (uint32_t)((lid & 7) + ((lid >> 4) * 8)) * 80
                    + (uint32_t)((lid >> 3) & 1) * 16;

    for (int i = 0; i < XNCH; i++) {
        CP_WAIT2();
        __syncthreads();
        if (i + 3 < XNCH) x_load_chunk(i + 3, sb_base, tid, VHb, AHb);
        CP_COMMIT();

        uint32_t sA = sb_base + (uint32_t)(i & (XSTAGES - 1)) * XSTAGE_BYTES;
        uint32_t sB = sA + EPLANE;

#pragma unroll
        for (int ks = 0; ks < 2; ks++) {
            uint32_t af[4][4];
#pragma unroll
            for (int mt = 0; mt < 4; mt++)
                ldm_x4(af[mt], sA + (uint32_t)(wm * 64 + mt * 16) * 80 + ks * 32 + a_lane);
            uint32_t bq[2][4];
#pragma unroll
            for (int p = 0; p < 2; p++)
                ldm_x4(bq[p], sB + (uint32_t)(wn * 32 + p * 16) * 80 + ks * 32 + b_lane);
#pragma unroll
            for (int mt = 0; mt < 4; mt++)
#pragma unroll
                for (int nt = 0; nt < 4; nt++)
                    mma_f16(acc[mt][nt], af[mt], &bq[nt >> 1][(nt & 1) * 2]);
        }
        __syncthreads();
    }
    CP_WAIT0();

#pragma unroll
    for (int mt = 0; mt < 4; mt++) {
        int r0 = i0 + wm * 64 + mt * 16 + g;
#pragma unroll
        for (int nt = 0; nt < 4; nt++) {
            int col = j0 + wn * 32 + nt * 8 + 2 * t;
            size_t off0 = ((size_t)b * CDIM + r0) * NDIM + col;
            size_t off1 = ((size_t)b * CDIM + r0 + 8) * NDIM + col;
            float2 t0 = {acc[mt][nt][0], acc[mt][nt][1]};
            float2 t1 = {acc[mt][nt][2], acc[mt][nt][3]};
            float2 s0 = *(const float2*)(SK + off0);
            float2 s1 = *(const float2*)(SK + off1);
            *(float2*)(TEX + off0) = t0;
            *(float2*)(TEX + off1) = t1;
            float2 o0 = {t0.x + s0.x, t0.y + s0.y};
            float2 o1 = {t1.x + s1.x, t1.y + s1.y};
            *(float2*)(OUT + off0) = o0;
            *(float2*)(OUT + off1) = o1;
        }
    }
}

// ---------------- launch (fork-join streams for projection overlap) ------------
extern "C" void kernel_launch(void* const* d_in, const int* in_sizes, int n_in,
                              void* d_out, int out_size)
{
    const float* sk = (const float*)d_in[0];
    const float* ex = (const float*)d_in[1];
    const float* Wq = (const float*)d_in[2];
    const float* bq = (const float*)d_in[3];
    const float* Wk = (const float*)d_in[4];
    const float* bk = (const float*)d_in[5];
    const float* Wv = (const float*)d_in[6];
    const float* bv = (const float*)d_in[7];

    const size_t BCN = (size_t)BATCH * CDIM * NDIM;
    const size_t BNN = (size_t)BATCH * NDIM * NDIM;

    float* out_p = (float*)d_out;
    float* tex_p;
    float* attn_p;

    if ((size_t)(unsigned)out_size >= 2 * BCN + BNN) {
        tex_p  = out_p + BCN;
        attn_p = out_p + 2 * BCN;
    } else {
        void* p;
        cudaGetSymbolAddress(&p, g_tex_fb);  tex_p  = (float*)p;
        cudaGetSymbolAddress(&p, g_attn_fb); attn_p = (float*)p;
    }

    __half *q_p, *k_p, *vh, *ah;
    { void* p;
      cudaGetSymbolAddress(&p, g_q);  q_p = (__half*)p;
      cudaGetSymbolAddress(&p, g_k);  k_p = (__half*)p;
      cudaGetSymbolAddress(&p, g_vh); vh  = (__half*)p;
      cudaGetSymbolAddress(&p, g_ah); ah  = (__half*)p; }

    // one-time resources (created on the uncaptured correctness call)
    static cudaStream_t s1 = nullptr, s2 = nullptr;
    static cudaEvent_t e_fork = nullptr, e_k = nullptr, e_v = nullptr;
    static int inited = 0;
    if (!inited) {
        cudaFuncSetAttribute(texture_mma_kernel,
                             cudaFuncAttributeMaxDynamicSharedMemorySize, XSMEM_BYTES);
        cudaStreamCreateWithFlags(&s1, cudaStreamNonBlocking);
        cudaStreamCreateWithFlags(&s2, cudaStreamNonBlocking);
        cudaEventCreateWithFlags(&e_fork, cudaEventDisableTiming);
        cudaEventCreateWithFlags(&e_k,    cudaEventDisableTiming);
        cudaEventCreateWithFlags(&e_v,    cudaEventDisableTiming);
        inited = 1;
    }

    dim3 gproj(NDIM / 256, BATCH);
    dim3 gv(NDIM / 128, CDIM / 64, BATCH);
    dim3 ga(NDIM / 128, BATCH);
    dim3 gt(NDIM / 128, CDIM / 128, BATCH);

    // fork
    cudaEventRecord(e_fork, 0);
    cudaStreamWaitEvent(s1, e_fork, 0);
    cudaStreamWaitEvent(s2, e_fork, 0);

    // s1: k projection;  s2: v projection;  stream0: q projection
    proj_small_kernel<<<gproj, 256, 0, s1>>>(ex, Wk, bk, k_p);
    cudaEventRecord(e_k, s1);
    proj_v_mma_kernel<<<gv, 256, 0, s2>>>(ex, Wv, bv, vh);
    cudaEventRecord(e_v, s2);
    proj_small_kernel<<<gproj, 256>>>(sk, Wq, bq, q_p);

    // attn needs q (stream0) + k (s1)
    cudaStreamWaitEvent(0, e_k, 0);
    attn_fused_kernel<<<ga, 256>>>(q_p, k_p, attn_p, ah);

    // texture needs attn (stream0) + v (s2)  -- join
    cudaStreamWaitEvent(0, e_v, 0);
    texture_mma_kernel<<<gt, 256, XSMEM_BYTES>>>(vh, ah, sk, tex_p, out_p);
}